// round 5
// baseline (speedup 1.0000x reference)
#include <cuda_runtime.h>
#include <cuda_bf16.h>
#include <cfloat>
#include <math.h>

// Problem constants
// B=2, N=2048, DIM=1024, HEADS=16, DH=64, PB_DIM=256
#define NB    2
#define NN    2048
#define NDIM  1024
#define NH    16
#define NDH   64
#define NPB   256
#define ROWS  (NB * NN)          // 4096
#define PBROWS (2 * NN - 1)      // 4095

// ---------------- scratch (device globals; no allocations allowed) -------------
__device__ float g_xn[ROWS * NDIM];            // 16.8 MB  RMSNorm output
__device__ float g_q[NB * NH * NN * NDH];      // 16.8 MB  [b,h,n,dh]
__device__ float g_k[NB * NH * NN * NDH];
__device__ float g_v[NB * NH * NN * NDH];
__device__ float g_pb[PBROWS * NH];            // 262 KB   [2n-1, H]
__device__ float g_maskadd[ROWS];              // 0 or -FLT_MAX per (b,n)
__device__ float g_attnout[ROWS * NDIM];       // 16.8 MB  [b,n,h*dh]
__device__ int   g_maskkind;                   // 0=u8 1=i32 2=f32

// ---------------- mask dtype detection --------------------------------------
// audio_mask is a jax bool; harness byte encoding is ambiguous. Inspect the
// first 4096 bytes (safe for u8 / i32 / f32 buffers of 4096 elements).
__global__ void detect_mask_kernel(const unsigned char* __restrict__ m) {
    __shared__ int ok_i32, ok_f32;
    if (threadIdx.x == 0) { ok_i32 = 1; ok_f32 = 1; }
    __syncthreads();
    int base = threadIdx.x * 16;
    int li = 1, lf = 1;
    for (int i = base; i < base + 16; i += 4) {
        unsigned char b0 = m[i], b1 = m[i + 1], b2 = m[i + 2], b3 = m[i + 3];
        if (!(b0 <= 1 && b1 == 0 && b2 == 0 && b3 == 0)) li = 0;
        bool fz = (b2 == 0 && b3 == 0);
        bool fo = (b2 == 0x80 && b3 == 0x3f);
        if (!(b0 == 0 && b1 == 0 && (fz || fo))) lf = 0;
    }
    if (!li) atomicAnd(&ok_i32, 0);
    if (!lf) atomicAnd(&ok_f32, 0);
    __syncthreads();
    if (threadIdx.x == 0) g_maskkind = ok_i32 ? 1 : (ok_f32 ? 2 : 0);
}

__global__ void expand_mask_kernel(const void* __restrict__ m) {
    int i = blockIdx.x * blockDim.x + threadIdx.x;
    if (i >= ROWS) return;
    int kind = g_maskkind;
    bool on;
    if (kind == 1)      on = ((const int*)m)[i] != 0;
    else if (kind == 2) on = ((const float*)m)[i] != 0.0f;
    else                on = ((const unsigned char*)m)[i] != 0;
    g_maskadd[i] = on ? 0.0f : -FLT_MAX;
}

// ---------------- RMSNorm ----------------------------------------------------
__global__ void rmsnorm_kernel(const float* __restrict__ x, const float* __restrict__ g) {
    __shared__ float red[8];
    int row = blockIdx.x;
    int tid = threadIdx.x;
    const float4* xr = (const float4*)(x + (size_t)row * NDIM);
    float4 xv = xr[tid];
    float ss = xv.x * xv.x + xv.y * xv.y + xv.z * xv.z + xv.w * xv.w;
#pragma unroll
    for (int off = 16; off; off >>= 1) ss += __shfl_xor_sync(0xffffffffu, ss, off);
    if ((tid & 31) == 0) red[tid >> 5] = ss;
    __syncthreads();
    float tot = red[0] + red[1] + red[2] + red[3] + red[4] + red[5] + red[6] + red[7];
    float inv = 32.0f / fmaxf(sqrtf(tot), 1e-12f);   // sqrt(1024)=32
    float4 gv = ((const float4*)g)[tid];
    float4 o;
    o.x = xv.x * inv * gv.x;
    o.y = xv.y * inv * gv.y;
    o.z = xv.z * inv * gv.z;
    o.w = xv.w * inv * gv.w;
    ((float4*)(g_xn + (size_t)row * NDIM))[tid] = o;
}

// ---------------- DynamicPositionBias MLP ------------------------------------
// 16 distance rows per CTA (so pb_w2 streams only 256x through L2).
__global__ void pb_mlp_kernel(const float* __restrict__ w1, const float* __restrict__ b1,
                              const float* __restrict__ w2, const float* __restrict__ b2,
                              const float* __restrict__ w3, const float* __restrict__ b3) {
    __shared__ float h1s[16][NPB];
    __shared__ float h2s[16][NPB];
    int t = threadIdx.x;
    int r0 = blockIdx.x * 16;
    float w1t = w1[t], b1t = b1[t];
#pragma unroll
    for (int rr = 0; rr < 16; rr++) {
        int r = r0 + rr;
        float pos = (float)(r - (NN - 1));
        float z = pos * w1t + b1t;
        h1s[rr][t] = (r < PBROWS) ? z / (1.0f + __expf(-z)) : 0.0f;
    }
    __syncthreads();
    float acc[16];
    float b2t = b2[t];
#pragma unroll
    for (int rr = 0; rr < 16; rr++) acc[rr] = b2t;
    for (int k2 = 0; k2 < NPB; k2++) {
        float w = w2[k2 * NPB + t];
#pragma unroll
        for (int rr = 0; rr < 16; rr++) acc[rr] = fmaf(h1s[rr][k2], w, acc[rr]);
    }
#pragma unroll
    for (int rr = 0; rr < 16; rr++) {
        float z = acc[rr];
        h2s[rr][t] = z / (1.0f + __expf(-z));
    }
    __syncthreads();
    {
        int rr = t >> 4, hh = t & 15;
        float a = b3[hh];
        for (int k2 = 0; k2 < NPB; k2++) a = fmaf(h2s[rr][k2], w3[k2 * NH + hh], a);
        int r = r0 + rr;
        if (r < PBROWS) g_pb[r * NH + hh] = a;
    }
}

// ---------------- SGEMM 128x128x8 (fp32) --------------------------------------
// MODE 0: C = g_xn @ w_qkv, routed into g_q/g_k/g_v in [b,h,n,dh] layout (N=3072)
// MODE 1: C = g_attnout @ w_out + b_out -> d_out (N=1024)
template <int MODE>
__global__ void __launch_bounds__(256, 2)
sgemm_kernel(const float* __restrict__ Bw, float* __restrict__ Cout,
             const float* __restrict__ bias, int N) {
    __shared__ float As[8][128];     // transposed A tile: As[k][m]
    __shared__ float Bs[8][132];     // Bs[k][n], padded
    const float* A = (MODE == 0) ? g_xn : g_attnout;
    const int K = NDIM;
    int m0 = blockIdx.y * 128;
    int n0 = blockIdx.x * 128;
    int tid = threadIdx.x;
    int tx = tid & 15, ty = tid >> 4;
    int arow = tid >> 1, acol = (tid & 1) * 4;
    int brow = tid >> 5, bcol = (tid & 31) * 4;

    float acc[8][8];
#pragma unroll
    for (int i = 0; i < 8; i++)
#pragma unroll
        for (int j = 0; j < 8; j++) acc[i][j] = 0.0f;

    float4 av = *(const float4*)(A + (size_t)(m0 + arow) * K + acol);
    float4 bv = *(const float4*)(Bw + (size_t)brow * N + n0 + bcol);

    for (int kt = 0; kt < K; kt += 8) {
        As[acol + 0][arow] = av.x;
        As[acol + 1][arow] = av.y;
        As[acol + 2][arow] = av.z;
        As[acol + 3][arow] = av.w;
        *(float4*)&Bs[brow][bcol] = bv;
        __syncthreads();
        if (kt + 8 < K) {
            av = *(const float4*)(A + (size_t)(m0 + arow) * K + (kt + 8) + acol);
            bv = *(const float4*)(Bw + (size_t)(kt + 8 + brow) * N + n0 + bcol);
        }
#pragma unroll
        for (int kk = 0; kk < 8; kk++) {
            float4 a0 = *(const float4*)&As[kk][ty * 4];
            float4 a1 = *(const float4*)&As[kk][64 + ty * 4];
            float4 b0 = *(const float4*)&Bs[kk][tx * 4];
            float4 b1 = *(const float4*)&Bs[kk][64 + tx * 4];
            float a[8] = {a0.x, a0.y, a0.z, a0.w, a1.x, a1.y, a1.z, a1.w};
            float bb[8] = {b0.x, b0.y, b0.z, b0.w, b1.x, b1.y, b1.z, b1.w};
#pragma unroll
            for (int i = 0; i < 8; i++)
#pragma unroll
                for (int j = 0; j < 8; j++) acc[i][j] = fmaf(a[i], bb[j], acc[i][j]);
        }
        __syncthreads();
    }

#pragma unroll
    for (int i = 0; i < 8; i++) {
        int rl = (i < 4) ? (ty * 4 + i) : (64 + ty * 4 + i - 4);
        int r = m0 + rl;
        if (MODE == 1) {
            int c0 = n0 + tx * 4;
            float4 s0 = make_float4(acc[i][0] + bias[c0], acc[i][1] + bias[c0 + 1],
                                    acc[i][2] + bias[c0 + 2], acc[i][3] + bias[c0 + 3]);
            *(float4*)(Cout + (size_t)r * N + c0) = s0;
            int c1 = n0 + 64 + tx * 4;
            float4 s1 = make_float4(acc[i][4] + bias[c1], acc[i][5] + bias[c1 + 1],
                                    acc[i][6] + bias[c1 + 2], acc[i][7] + bias[c1 + 3]);
            *(float4*)(Cout + (size_t)r * N + c1) = s1;
        } else {
#pragma unroll
            for (int j = 0; j < 8; j++) {
                int cl = (j < 4) ? (tx * 4 + j) : (64 + tx * 4 + j - 4);
                int gc = n0 + cl;
                int b = r >> 11, n = r & (NN - 1);
                int which = gc >> 10, cc = gc & 1023;
                int h = cc >> 6, d = cc & 63;
                float* dst = (which == 0) ? g_q : (which == 1) ? g_k : g_v;
                dst[(((b * NH + h) * NN) + n) * NDH + d] = acc[i][j];
            }
        }
    }
}

// ---------------- Flash attention with relative-position bias + mask ----------
// Tile: BM=128 query rows x BN=64 key cols, 256 threads, fp32 fragments 8x4.
__device__ __forceinline__ float redmax16(float v) {
    v = fmaxf(v, __shfl_xor_sync(0xffffffffu, v, 8));
    v = fmaxf(v, __shfl_xor_sync(0xffffffffu, v, 4));
    v = fmaxf(v, __shfl_xor_sync(0xffffffffu, v, 2));
    v = fmaxf(v, __shfl_xor_sync(0xffffffffu, v, 1));
    return v;
}
__device__ __forceinline__ float redsum16(float v) {
    v += __shfl_xor_sync(0xffffffffu, v, 8);
    v += __shfl_xor_sync(0xffffffffu, v, 4);
    v += __shfl_xor_sync(0xffffffffu, v, 2);
    v += __shfl_xor_sync(0xffffffffu, v, 1);
    return v;
}

#define ATT_QT_LD 132
#define ATT_KT_LD 68
#define ATT_SMEM_FLOATS (64*132 + 64*68 + 64*68 + 64*132 + 192 + 64)
#define ATT_SMEM_BYTES  (ATT_SMEM_FLOATS * 4)

__global__ void __launch_bounds__(256, 2) attn_kernel() {
    extern __shared__ float smf[];
    float* qT  = smf;                    // [64][132]  qT[d][i]
    float* kT  = qT + 64 * ATT_QT_LD;    // [64][68]   kT[d][j]
    float* vS  = kT + 64 * ATT_KT_LD;    // [64][68]   v[j][d]
    float* pT  = vS + 64 * ATT_KT_LD;    // [64][132]  pT[j][i]
    float* pbt = pT + 64 * ATT_QT_LD;    // [192]      bias diagonal slice
    float* mkt = pbt + 192;              // [64]       mask add per j

    const int tid = threadIdx.x;
    const int ti = tid >> 4, tc = tid & 15;
    const int ri = ti * 8;               // 8 query rows per thread
    const int cj = tc * 4;               // 4 score cols / 4 O dims per thread
    const int bh = blockIdx.y;
    const int b = bh >> 4, h = bh & 15;
    const int i0 = blockIdx.x * 128;
    const float* qg = g_q + (size_t)bh * (NN * NDH);
    const float* kg = g_k + (size_t)bh * (NN * NDH);
    const float* vg = g_v + (size_t)bh * (NN * NDH);

    // load Q tile transposed into smem
#pragma unroll
    for (int it = 0; it < 8; it++) {
        int idx = tid + it * 256;
        int row = idx >> 4;
        int d4 = (idx & 15) * 4;
        float4 qv = *(const float4*)(qg + (size_t)(i0 + row) * NDH + d4);
        qT[(d4 + 0) * ATT_QT_LD + row] = qv.x;
        qT[(d4 + 1) * ATT_QT_LD + row] = qv.y;
        qT[(d4 + 2) * ATT_QT_LD + row] = qv.z;
        qT[(d4 + 3) * ATT_QT_LD + row] = qv.w;
    }

    float o[8][4];
    float mrow[8], lrow[8];
#pragma unroll
    for (int r = 0; r < 8; r++) {
        mrow[r] = -FLT_MAX; lrow[r] = 0.0f;
#pragma unroll
        for (int c = 0; c < 4; c++) o[r][c] = 0.0f;
    }

    const float scl = 0.125f;  // 1/sqrt(64)

    for (int jt = 0; jt < NN / 64; jt++) {
        int j0 = jt * 64;
        // load K tile (transposed) and V tile
#pragma unroll
        for (int it = 0; it < 4; it++) {
            int idx = tid + it * 256;
            int row = idx >> 4;
            int d4 = (idx & 15) * 4;
            float4 kv = *(const float4*)(kg + (size_t)(j0 + row) * NDH + d4);
            kT[(d4 + 0) * ATT_KT_LD + row] = kv.x;
            kT[(d4 + 1) * ATT_KT_LD + row] = kv.y;
            kT[(d4 + 2) * ATT_KT_LD + row] = kv.z;
            kT[(d4 + 3) * ATT_KT_LD + row] = kv.w;
            float4 vv = *(const float4*)(vg + (size_t)(j0 + row) * NDH + d4);
            *(float4*)(vS + row * ATT_KT_LD + d4) = vv;
        }
        // bias diagonal slice: pbrow = (i-j)+2047 = (i0-j0+1984) + t, t = (r-c)+63 in [0,190]
        if (tid < 191) pbt[tid] = g_pb[(i0 - j0 + 1984 + tid) * NH + h];
        if (tid < 64) mkt[tid] = g_maskadd[b * NN + j0 + tid];
        __syncthreads();   // (A) tiles visible

        // S = Q K^T  (8x4 fragment per thread)
        float s[8][4];
#pragma unroll
        for (int r = 0; r < 8; r++)
#pragma unroll
            for (int c = 0; c < 4; c++) s[r][c] = 0.0f;
#pragma unroll 16
        for (int d = 0; d < 64; d++) {
            float4 a0 = *(const float4*)(qT + d * ATT_QT_LD + ri);
            float4 a1 = *(const float4*)(qT + d * ATT_QT_LD + ri + 4);
            float4 bk = *(const float4*)(kT + d * ATT_KT_LD + cj);
            float a[8] = {a0.x, a0.y, a0.z, a0.w, a1.x, a1.y, a1.z, a1.w};
            float bb[4] = {bk.x, bk.y, bk.z, bk.w};
#pragma unroll
            for (int r = 0; r < 8; r++)
#pragma unroll
                for (int c = 0; c < 4; c++) s[r][c] = fmaf(a[r], bb[c], s[r][c]);
        }

        // scale + bias + mask, online softmax
#pragma unroll
        for (int r = 0; r < 8; r++) {
            float mx = -FLT_MAX;
#pragma unroll
            for (int c = 0; c < 4; c++) {
                float addv = pbt[(ri + r) - (cj + c) + 63] + mkt[cj + c];
                float val = fmaf(s[r][c], scl, addv);
                s[r][c] = val;
                mx = fmaxf(mx, val);
            }
            mx = redmax16(mx);
            float mn = fmaxf(mrow[r], mx);
            float al = __expf(mrow[r] - mn);
            mrow[r] = mn;
            float rs = 0.0f;
#pragma unroll
            for (int c = 0; c < 4; c++) {
                float p = __expf(s[r][c] - mn);
                s[r][c] = p;
                rs += p;
            }
            rs = redsum16(rs);
            lrow[r] = lrow[r] * al + rs;
#pragma unroll
            for (int c = 0; c < 4; c++) o[r][c] *= al;
        }

        // store P transposed: pT[j][i]
#pragma unroll
        for (int c = 0; c < 4; c++) {
            *(float4*)(pT + (cj + c) * ATT_QT_LD + ri) =
                make_float4(s[0][c], s[1][c], s[2][c], s[3][c]);
            *(float4*)(pT + (cj + c) * ATT_QT_LD + ri + 4) =
                make_float4(s[4][c], s[5][c], s[6][c], s[7][c]);
        }
        __syncthreads();   // (B) P visible

        // O += P V  (thread covers 8 rows x 4 head-dims cj..cj+3)
#pragma unroll 8
        for (int j = 0; j < 64; j++) {
            float4 p0 = *(const float4*)(pT + j * ATT_QT_LD + ri);
            float4 p1 = *(const float4*)(pT + j * ATT_QT_LD + ri + 4);
            float4 vv = *(const float4*)(vS + j * ATT_KT_LD + cj);
            float p[8] = {p0.x, p0.y, p0.z, p0.w, p1.x, p1.y, p1.z, p1.w};
#pragma unroll
            for (int r = 0; r < 8; r++) {
                o[r][0] = fmaf(p[r], vv.x, o[r][0]);
                o[r][1] = fmaf(p[r], vv.y, o[r][1]);
                o[r][2] = fmaf(p[r], vv.z, o[r][2]);
                o[r][3] = fmaf(p[r], vv.w, o[r][3]);
            }
        }
        __syncthreads();   // (C) done reading pT/vS before next tile loads
    }

    // finalize: write [b, n, h*64 + d]
    float* og = g_attnout + (size_t)(b * NN + i0) * NDIM + h * NDH;
#pragma unroll
    for (int r = 0; r < 8; r++) {
        float invl = 1.0f / lrow[r];
        *(float4*)(og + (size_t)(ri + r) * NDIM + cj) =
            make_float4(o[r][0] * invl, o[r][1] * invl, o[r][2] * invl, o[r][3] * invl);
    }
}

// ---------------- launch ------------------------------------------------------
extern "C" void kernel_launch(void* const* d_in, const int* in_sizes, int n_in,
                              void* d_out, int out_size) {
    const float* x      = (const float*)d_in[0];
    const void*  mask   = d_in[1];
    const float* g      = (const float*)d_in[2];
    const float* w_qkv  = (const float*)d_in[3];
    const float* w_out  = (const float*)d_in[4];
    const float* b_out  = (const float*)d_in[5];
    const float* pb_w1  = (const float*)d_in[6];
    const float* pb_b1  = (const float*)d_in[7];
    const float* pb_w2  = (const float*)d_in[8];
    const float* pb_b2  = (const float*)d_in[9];
    const float* pb_w3  = (const float*)d_in[10];
    const float* pb_b3  = (const float*)d_in[11];
    float* out = (float*)d_out;

    detect_mask_kernel<<<1, 256>>>((const unsigned char*)mask);
    expand_mask_kernel<<<ROWS / 256, 256>>>(mask);
    rmsnorm_kernel<<<ROWS, 256>>>(x, g);
    pb_mlp_kernel<<<256, 256>>>(pb_w1, pb_b1, pb_w2, pb_b2, pb_w3, pb_b3);

    // QKV GEMM: [4096,1024] @ [1024,3072]
    sgemm_kernel<0><<<dim3(3 * NDIM / 128, ROWS / 128), 256>>>(w_qkv, nullptr, nullptr, 3 * NDIM);

    // Flash attention
    cudaFuncSetAttribute(attn_kernel, cudaFuncAttributeMaxDynamicSharedMemorySize, ATT_SMEM_BYTES);
    attn_kernel<<<dim3(NN / 128, NB * NH), 256, ATT_SMEM_BYTES>>>();

    // Output projection: [4096,1024] @ [1024,1024] + b_out
    sgemm_kernel<1><<<dim3(NDIM / 128, ROWS / 128), 256>>>(w_out, out, b_out, NDIM);
}

// round 6
// speedup vs baseline: 1.3304x; 1.3304x over previous
#include <cuda_runtime.h>
#include <cuda_bf16.h>
#include <cfloat>
#include <math.h>
#include <stdint.h>

// Problem constants
// B=2, N=2048, DIM=1024, HEADS=16, DH=64, PB_DIM=256
#define NB    2
#define NN    2048
#define NDIM  1024
#define NH    16
#define NDH   64
#define NPB   256
#define ROWS  (NB * NN)          // 4096
#define PBROWS (2 * NN - 1)      // 4095

// ---------------- scratch (device globals; no allocations allowed) -------------
__device__ float g_xn[ROWS * NDIM];            // 16.8 MB  RMSNorm output
__device__ float g_q[NB * NH * NN * NDH];      // 16.8 MB  [b,h,n,dh]
__device__ float g_k[NB * NH * NN * NDH];
__device__ float g_v[NB * NH * NN * NDH];
__device__ float g_pb[PBROWS * NH];            // 262 KB   [2n-1, H]
__device__ float g_maskadd[ROWS];              // 0 or -FLT_MAX per (b,n)
__device__ float g_attnout[ROWS * NDIM];       // 16.8 MB  [b,n,h*dh]
__device__ int   g_maskkind;                   // 0=u8 1=i32 2=f32

// ---------------- mask dtype detection --------------------------------------
__global__ void detect_mask_kernel(const unsigned char* __restrict__ m) {
    __shared__ int ok_i32, ok_f32;
    if (threadIdx.x == 0) { ok_i32 = 1; ok_f32 = 1; }
    __syncthreads();
    int base = threadIdx.x * 16;
    int li = 1, lf = 1;
    for (int i = base; i < base + 16; i += 4) {
        unsigned char b0 = m[i], b1 = m[i + 1], b2 = m[i + 2], b3 = m[i + 3];
        if (!(b0 <= 1 && b1 == 0 && b2 == 0 && b3 == 0)) li = 0;
        bool fz = (b2 == 0 && b3 == 0);
        bool fo = (b2 == 0x80 && b3 == 0x3f);
        if (!(b0 == 0 && b1 == 0 && (fz || fo))) lf = 0;
    }
    if (!li) atomicAnd(&ok_i32, 0);
    if (!lf) atomicAnd(&ok_f32, 0);
    __syncthreads();
    if (threadIdx.x == 0) g_maskkind = ok_i32 ? 1 : (ok_f32 ? 2 : 0);
}

__global__ void expand_mask_kernel(const void* __restrict__ m) {
    int i = blockIdx.x * blockDim.x + threadIdx.x;
    if (i >= ROWS) return;
    int kind = g_maskkind;
    bool on;
    if (kind == 1)      on = ((const int*)m)[i] != 0;
    else if (kind == 2) on = ((const float*)m)[i] != 0.0f;
    else                on = ((const unsigned char*)m)[i] != 0;
    g_maskadd[i] = on ? 0.0f : -FLT_MAX;
}

// ---------------- RMSNorm ----------------------------------------------------
__global__ void rmsnorm_kernel(const float* __restrict__ x, const float* __restrict__ g) {
    __shared__ float red[8];
    int row = blockIdx.x;
    int tid = threadIdx.x;
    const float4* xr = (const float4*)(x + (size_t)row * NDIM);
    float4 xv = xr[tid];
    float ss = xv.x * xv.x + xv.y * xv.y + xv.z * xv.z + xv.w * xv.w;
#pragma unroll
    for (int off = 16; off; off >>= 1) ss += __shfl_xor_sync(0xffffffffu, ss, off);
    if ((tid & 31) == 0) red[tid >> 5] = ss;
    __syncthreads();
    float tot = red[0] + red[1] + red[2] + red[3] + red[4] + red[5] + red[6] + red[7];
    float inv = 32.0f / fmaxf(sqrtf(tot), 1e-12f);   // sqrt(1024)=32
    float4 gv = ((const float4*)g)[tid];
    float4 o;
    o.x = xv.x * inv * gv.x;
    o.y = xv.y * inv * gv.y;
    o.z = xv.z * inv * gv.z;
    o.w = xv.w * inv * gv.w;
    ((float4*)(g_xn + (size_t)row * NDIM))[tid] = o;
}

// ---------------- DynamicPositionBias MLP ------------------------------------
__global__ void pb_mlp_kernel(const float* __restrict__ w1, const float* __restrict__ b1,
                              const float* __restrict__ w2, const float* __restrict__ b2,
                              const float* __restrict__ w3, const float* __restrict__ b3) {
    __shared__ float h1s[16][NPB];
    __shared__ float h2s[16][NPB];
    int t = threadIdx.x;
    int r0 = blockIdx.x * 16;
    float w1t = w1[t], b1t = b1[t];
#pragma unroll
    for (int rr = 0; rr < 16; rr++) {
        int r = r0 + rr;
        float pos = (float)(r - (NN - 1));
        float z = pos * w1t + b1t;
        h1s[rr][t] = (r < PBROWS) ? z / (1.0f + __expf(-z)) : 0.0f;
    }
    __syncthreads();
    float acc[16];
    float b2t = b2[t];
#pragma unroll
    for (int rr = 0; rr < 16; rr++) acc[rr] = b2t;
#pragma unroll 4
    for (int k2 = 0; k2 < NPB; k2++) {
        float w = w2[k2 * NPB + t];
#pragma unroll
        for (int rr = 0; rr < 16; rr++) acc[rr] = fmaf(h1s[rr][k2], w, acc[rr]);
    }
#pragma unroll
    for (int rr = 0; rr < 16; rr++) {
        float z = acc[rr];
        h2s[rr][t] = z / (1.0f + __expf(-z));
    }
    __syncthreads();
    {
        int rr = t >> 4, hh = t & 15;
        float a = b3[hh];
        for (int k2 = 0; k2 < NPB; k2++) a = fmaf(h2s[rr][k2], w3[k2 * NH + hh], a);
        int r = r0 + rr;
        if (r < PBROWS) g_pb[r * NH + hh] = a;
    }
}

// ---------------- tf32 tensor-core GEMM 128x128x16 ----------------------------
// MODE 0: C = g_xn @ w_qkv, routed into g_q/g_k/g_v in [b,h,n,dh] layout (N=3072)
// MODE 1: C = g_attnout @ w_out + b_out -> d_out (N=1024)
//
// smem: As[k][m] and Bs[k][n], LD = 136 (== 8 mod 32) -> fragment LDS bank =
// 8*(lane&3) + (lane>>2) + const -> conflict-free. A stores swizzled:
// m' = m ^ (8*((k>>2)&3)); at every fragment-load site (k>>2)&3 is
// lane-invariant, so loads stay conflict-free while stores become so too.

#define GLD 136

__device__ __forceinline__ uint32_t f2tf32(float x) {
    uint32_t u;
    asm("cvt.rna.tf32.f32 %0, %1;" : "=r"(u) : "f"(x));
    return u;
}

__device__ __forceinline__ void mma_tf32(float c[4], const uint32_t a[4], const uint32_t b[2]) {
    asm volatile(
        "mma.sync.aligned.m16n8k8.row.col.f32.tf32.tf32.f32 "
        "{%0,%1,%2,%3}, {%4,%5,%6,%7}, {%8,%9}, {%0,%1,%2,%3};\n"
        : "+f"(c[0]), "+f"(c[1]), "+f"(c[2]), "+f"(c[3])
        : "r"(a[0]), "r"(a[1]), "r"(a[2]), "r"(a[3]), "r"(b[0]), "r"(b[1]));
}

template <int MODE>
__global__ void __launch_bounds__(256, 2)
mma_gemm_kernel(const float* __restrict__ Bw, float* __restrict__ Cout,
                const float* __restrict__ bias, int N) {
    __shared__ uint32_t As[16 * GLD];   // As[k][m], swizzled m
    __shared__ uint32_t Bs[16 * GLD];   // Bs[k][n]
    const float* A = (MODE == 0) ? g_xn : g_attnout;
    const int K = NDIM;
    const int m0 = blockIdx.y * 128;
    const int n0 = blockIdx.x * 128;
    const int tid  = threadIdx.x;
    const int warp = tid >> 5, lane = tid & 31;
    const int warpM = (warp >> 1) * 32;   // 4 warps along m
    const int warpN = (warp & 1) * 64;    // 2 warps along n

    // loader indices
    const int ar  = tid >> 2;          // 0..63 (A rows; also ar+64)
    const int akc = (tid & 3) * 4;     // A k-offset {0,4,8,12}
    const int asw = ar ^ (8 * (tid & 3));        // swizzled store col (k>>2 == tid&3)
    const int asw2 = (ar + 64) ^ (8 * (tid & 3));
    const int bk  = tid >> 5;          // 0..7 (B k rows; also bk+8)
    const int bn4 = lane * 4;          // B col offset

    float4 pa0, pa1, pb0, pb1;
    pa0 = *(const float4*)(A + (size_t)(m0 + ar) * K + akc);
    pa1 = *(const float4*)(A + (size_t)(m0 + ar + 64) * K + akc);
    pb0 = *(const float4*)(Bw + (size_t)bk * N + n0 + bn4);
    pb1 = *(const float4*)(Bw + (size_t)(bk + 8) * N + n0 + bn4);

    float c[2][8][4];
#pragma unroll
    for (int mt = 0; mt < 2; mt++)
#pragma unroll
        for (int nt = 0; nt < 8; nt++)
#pragma unroll
            for (int i = 0; i < 4; i++) c[mt][nt][i] = 0.0f;

    for (int kt = 0; kt < K; kt += 16) {
        // stores (tf32-converted)
        {
            float af0[4] = {pa0.x, pa0.y, pa0.z, pa0.w};
            float af1[4] = {pa1.x, pa1.y, pa1.z, pa1.w};
#pragma unroll
            for (int i = 0; i < 4; i++) {
                As[(akc + i) * GLD + asw]  = f2tf32(af0[i]);
                As[(akc + i) * GLD + asw2] = f2tf32(af1[i]);
            }
            uint4 b0 = make_uint4(f2tf32(pb0.x), f2tf32(pb0.y), f2tf32(pb0.z), f2tf32(pb0.w));
            uint4 b1 = make_uint4(f2tf32(pb1.x), f2tf32(pb1.y), f2tf32(pb1.z), f2tf32(pb1.w));
            *(uint4*)&Bs[bk * GLD + bn4]       = b0;
            *(uint4*)&Bs[(bk + 8) * GLD + bn4] = b1;
        }
        __syncthreads();
        if (kt + 16 < K) {
            pa0 = *(const float4*)(A + (size_t)(m0 + ar) * K + (kt + 16) + akc);
            pa1 = *(const float4*)(A + (size_t)(m0 + ar + 64) * K + (kt + 16) + akc);
            pb0 = *(const float4*)(Bw + (size_t)(kt + 16 + bk) * N + n0 + bn4);
            pb1 = *(const float4*)(Bw + (size_t)(kt + 16 + bk + 8) * N + n0 + bn4);
        }
#pragma unroll
        for (int kk = 0; kk < 16; kk += 8) {
            const int kb  = kk + (lane & 3);
            const int kb4 = kb + 4;
            const int s1 = 8 * ((kb >> 2) & 3);   // lane-invariant (kb in one 4-group)
            const int s2 = 8 * ((kb4 >> 2) & 3);
            uint32_t a[2][4];
#pragma unroll
            for (int mt = 0; mt < 2; mt++) {
                int r = warpM + mt * 16 + (lane >> 2);
                a[mt][0] = As[kb * GLD + (r ^ s1)];
                a[mt][1] = As[kb * GLD + ((r + 8) ^ s1)];
                a[mt][2] = As[kb4 * GLD + (r ^ s2)];
                a[mt][3] = As[kb4 * GLD + ((r + 8) ^ s2)];
            }
            uint32_t b[8][2];
#pragma unroll
            for (int nt = 0; nt < 8; nt++) {
                int cb = warpN + nt * 8 + (lane >> 2);
                b[nt][0] = Bs[kb * GLD + cb];
                b[nt][1] = Bs[kb4 * GLD + cb];
            }
#pragma unroll
            for (int mt = 0; mt < 2; mt++)
#pragma unroll
                for (int nt = 0; nt < 8; nt++)
                    mma_tf32(c[mt][nt], a[mt], b[nt]);
        }
        __syncthreads();
    }

    // epilogue
#pragma unroll
    for (int mt = 0; mt < 2; mt++) {
#pragma unroll
        for (int h2 = 0; h2 < 2; h2++) {
            int r = m0 + warpM + mt * 16 + (lane >> 2) + h2 * 8;
            if (MODE == 1) {
#pragma unroll
                for (int nt = 0; nt < 8; nt++) {
                    int gc = n0 + warpN + nt * 8 + 2 * (lane & 3);
                    float2 v = make_float2(c[mt][nt][h2 * 2 + 0] + bias[gc],
                                           c[mt][nt][h2 * 2 + 1] + bias[gc + 1]);
                    *(float2*)(Cout + (size_t)r * N + gc) = v;
                }
            } else {
                int bidx = r >> 11, n = r & (NN - 1);
#pragma unroll
                for (int nt = 0; nt < 8; nt++) {
                    int gc = n0 + warpN + nt * 8 + 2 * (lane & 3);
                    int which = gc >> 10, cc = gc & 1023;
                    int h = cc >> 6, d = cc & 63;
                    float* dst = (which == 0) ? g_q : (which == 1) ? g_k : g_v;
                    float2 v = make_float2(c[mt][nt][h2 * 2 + 0], c[mt][nt][h2 * 2 + 1]);
                    *(float2*)(dst + (size_t)(((bidx * NH + h) * NN) + n) * NDH + d) = v;
                }
            }
        }
    }
}

// ---------------- Flash attention with relative-position bias + mask ----------
__device__ __forceinline__ float redmax16(float v) {
    v = fmaxf(v, __shfl_xor_sync(0xffffffffu, v, 8));
    v = fmaxf(v, __shfl_xor_sync(0xffffffffu, v, 4));
    v = fmaxf(v, __shfl_xor_sync(0xffffffffu, v, 2));
    v = fmaxf(v, __shfl_xor_sync(0xffffffffu, v, 1));
    return v;
}
__device__ __forceinline__ float redsum16(float v) {
    v += __shfl_xor_sync(0xffffffffu, v, 8);
    v += __shfl_xor_sync(0xffffffffu, v, 4);
    v += __shfl_xor_sync(0xffffffffu, v, 2);
    v += __shfl_xor_sync(0xffffffffu, v, 1);
    return v;
}

#define ATT_QT_LD 132
#define ATT_KT_LD 68
#define ATT_SMEM_FLOATS (64*132 + 64*68 + 64*68 + 64*132 + 192 + 64)
#define ATT_SMEM_BYTES  (ATT_SMEM_FLOATS * 4)

__global__ void __launch_bounds__(256, 2) attn_kernel() {
    extern __shared__ float smf[];
    float* qT  = smf;                    // [64][132]  qT[d][i]
    float* kT  = qT + 64 * ATT_QT_LD;    // [64][68]   kT[d][j]
    float* vS  = kT + 64 * ATT_KT_LD;    // [64][68]   v[j][d]
    float* pT  = vS + 64 * ATT_KT_LD;    // [64][132]  pT[j][i]
    float* pbt = pT + 64 * ATT_QT_LD;    // [192]      bias diagonal slice
    float* mkt = pbt + 192;              // [64]       mask add per j

    const int tid = threadIdx.x;
    const int ti = tid >> 4, tc = tid & 15;
    const int ri = ti * 8;               // 8 query rows per thread
    const int cj = tc * 4;               // 4 score cols / 4 O dims per thread
    const int bh = blockIdx.y;
    const int b = bh >> 4, h = bh & 15;
    const int i0 = blockIdx.x * 128;
    const float* qg = g_q + (size_t)bh * (NN * NDH);
    const float* kg = g_k + (size_t)bh * (NN * NDH);
    const float* vg = g_v + (size_t)bh * (NN * NDH);

    // load Q tile transposed into smem
#pragma unroll
    for (int it = 0; it < 8; it++) {
        int idx = tid + it * 256;
        int row = idx >> 4;
        int d4 = (idx & 15) * 4;
        float4 qv = *(const float4*)(qg + (size_t)(i0 + row) * NDH + d4);
        qT[(d4 + 0) * ATT_QT_LD + row] = qv.x;
        qT[(d4 + 1) * ATT_QT_LD + row] = qv.y;
        qT[(d4 + 2) * ATT_QT_LD + row] = qv.z;
        qT[(d4 + 3) * ATT_QT_LD + row] = qv.w;
    }

    float o[8][4];
    float mrow[8], lrow[8];
#pragma unroll
    for (int r = 0; r < 8; r++) {
        mrow[r] = -FLT_MAX; lrow[r] = 0.0f;
#pragma unroll
        for (int c = 0; c < 4; c++) o[r][c] = 0.0f;
    }

    const float scl = 0.125f;  // 1/sqrt(64)

    for (int jt = 0; jt < NN / 64; jt++) {
        int j0 = jt * 64;
#pragma unroll
        for (int it = 0; it < 4; it++) {
            int idx = tid + it * 256;
            int row = idx >> 4;
            int d4 = (idx & 15) * 4;
            float4 kv = *(const float4*)(kg + (size_t)(j0 + row) * NDH + d4);
            kT[(d4 + 0) * ATT_KT_LD + row] = kv.x;
            kT[(d4 + 1) * ATT_KT_LD + row] = kv.y;
            kT[(d4 + 2) * ATT_KT_LD + row] = kv.z;
            kT[(d4 + 3) * ATT_KT_LD + row] = kv.w;
            float4 vv = *(const float4*)(vg + (size_t)(j0 + row) * NDH + d4);
            *(float4*)(vS + row * ATT_KT_LD + d4) = vv;
        }
        if (tid < 191) pbt[tid] = g_pb[(i0 - j0 + 1984 + tid) * NH + h];
        if (tid < 64) mkt[tid] = g_maskadd[b * NN + j0 + tid];
        __syncthreads();   // (A) tiles visible

        // S = Q K^T  (8x4 fragment per thread)
        float s[8][4];
#pragma unroll
        for (int r = 0; r < 8; r++)
#pragma unroll
            for (int c = 0; c < 4; c++) s[r][c] = 0.0f;
#pragma unroll 16
        for (int d = 0; d < 64; d++) {
            float4 a0 = *(const float4*)(qT + d * ATT_QT_LD + ri);
            float4 a1 = *(const float4*)(qT + d * ATT_QT_LD + ri + 4);
            float4 bk = *(const float4*)(kT + d * ATT_KT_LD + cj);
            float a[8] = {a0.x, a0.y, a0.z, a0.w, a1.x, a1.y, a1.z, a1.w};
            float bb[4] = {bk.x, bk.y, bk.z, bk.w};
#pragma unroll
            for (int r = 0; r < 8; r++)
#pragma unroll
                for (int c = 0; c < 4; c++) s[r][c] = fmaf(a[r], bb[c], s[r][c]);
        }

        // scale + bias + mask, online softmax
#pragma unroll
        for (int r = 0; r < 8; r++) {
            float mx = -FLT_MAX;
#pragma unroll
            for (int c = 0; c < 4; c++) {
                float addv = pbt[(ri + r) - (cj + c) + 63] + mkt[cj + c];
                float val = fmaf(s[r][c], scl, addv);
                s[r][c] = val;
                mx = fmaxf(mx, val);
            }
            mx = redmax16(mx);
            float mn = fmaxf(mrow[r], mx);
            float al = __expf(mrow[r] - mn);
            mrow[r] = mn;
            float rs = 0.0f;
#pragma unroll
            for (int c = 0; c < 4; c++) {
                float p = __expf(s[r][c] - mn);
                s[r][c] = p;
                rs += p;
            }
            rs = redsum16(rs);
            lrow[r] = lrow[r] * al + rs;
#pragma unroll
            for (int c = 0; c < 4; c++) o[r][c] *= al;
        }

        // store P transposed: pT[j][i]
#pragma unroll
        for (int c = 0; c < 4; c++) {
            *(float4*)(pT + (cj + c) * ATT_QT_LD + ri) =
                make_float4(s[0][c], s[1][c], s[2][c], s[3][c]);
            *(float4*)(pT + (cj + c) * ATT_QT_LD + ri + 4) =
                make_float4(s[4][c], s[5][c], s[6][c], s[7][c]);
        }
        __syncthreads();   // (B) P visible

        // O += P V
#pragma unroll 8
        for (int j = 0; j < 64; j++) {
            float4 p0 = *(const float4*)(pT + j * ATT_QT_LD + ri);
            float4 p1 = *(const float4*)(pT + j * ATT_QT_LD + ri + 4);
            float4 vv = *(const float4*)(vS + j * ATT_KT_LD + cj);
            float p[8] = {p0.x, p0.y, p0.z, p0.w, p1.x, p1.y, p1.z, p1.w};
#pragma unroll
            for (int r = 0; r < 8; r++) {
                o[r][0] = fmaf(p[r], vv.x, o[r][0]);
                o[r][1] = fmaf(p[r], vv.y, o[r][1]);
                o[r][2] = fmaf(p[r], vv.z, o[r][2]);
                o[r][3] = fmaf(p[r], vv.w, o[r][3]);
            }
        }
        __syncthreads();   // (C) done reading pT/vS before next tile loads
    }

    // finalize: write [b, n, h*64 + d]
    float* og = g_attnout + (size_t)(b * NN + i0) * NDIM + h * NDH;
#pragma unroll
    for (int r = 0; r < 8; r++) {
        float invl = 1.0f / lrow[r];
        *(float4*)(og + (size_t)(ri + r) * NDIM + cj) =
            make_float4(o[r][0] * invl, o[r][1] * invl, o[r][2] * invl, o[r][3] * invl);
    }
}

// ---------------- launch ------------------------------------------------------
extern "C" void kernel_launch(void* const* d_in, const int* in_sizes, int n_in,
                              void* d_out, int out_size) {
    const float* x      = (const float*)d_in[0];
    const void*  mask   = d_in[1];
    const float* g      = (const float*)d_in[2];
    const float* w_qkv  = (const float*)d_in[3];
    const float* w_out  = (const float*)d_in[4];
    const float* b_out  = (const float*)d_in[5];
    const float* pb_w1  = (const float*)d_in[6];
    const float* pb_b1  = (const float*)d_in[7];
    const float* pb_w2  = (const float*)d_in[8];
    const float* pb_b2  = (const float*)d_in[9];
    const float* pb_w3  = (const float*)d_in[10];
    const float* pb_b3  = (const float*)d_in[11];
    float* out = (float*)d_out;

    detect_mask_kernel<<<1, 256>>>((const unsigned char*)mask);
    expand_mask_kernel<<<ROWS / 256, 256>>>(mask);
    rmsnorm_kernel<<<ROWS, 256>>>(x, g);
    pb_mlp_kernel<<<256, 256>>>(pb_w1, pb_b1, pb_w2, pb_b2, pb_w3, pb_b3);

    // QKV GEMM: [4096,1024] @ [1024,3072]  (tf32 tensor cores)
    mma_gemm_kernel<0><<<dim3(3 * NDIM / 128, ROWS / 128), 256>>>(w_qkv, nullptr, nullptr, 3 * NDIM);

    // Flash attention
    cudaFuncSetAttribute(attn_kernel, cudaFuncAttributeMaxDynamicSharedMemorySize, ATT_SMEM_BYTES);
    attn_kernel<<<dim3(NN / 128, NB * NH), 256, ATT_SMEM_BYTES>>>();

    // Output projection: [4096,1024] @ [1024,1024] + b_out  (tf32 tensor cores)
    mma_gemm_kernel<1><<<dim3(NDIM / 128, ROWS / 128), 256>>>(w_out, out, b_out, NDIM);
}

// round 8
// speedup vs baseline: 2.2863x; 1.7185x over previous
#include <cuda_runtime.h>
#include <cuda_bf16.h>
#include <cfloat>
#include <math.h>
#include <stdint.h>

// Problem constants
// B=2, N=2048, DIM=1024, HEADS=16, DH=64, PB_DIM=256
#define NB    2
#define NN    2048
#define NDIM  1024
#define NH    16
#define NDH   64
#define NPB   256
#define ROWS  (NB * NN)          // 4096
#define PBROWS (2 * NN - 1)      // 4095

// ---------------- scratch (device globals; no allocations allowed) -------------
__device__ float g_xn[ROWS * NDIM];            // 16.8 MB  RMSNorm output
__device__ float g_q[NB * NH * NN * NDH];      // 16.8 MB  [b,h,n,dh]
__device__ float g_k[NB * NH * NN * NDH];
__device__ float g_v[NB * NH * NN * NDH];
__device__ float g_pb[PBROWS * NH];            // 262 KB   [2n-1, H]
__device__ float g_maskadd[ROWS];              // 0 or -FLT_MAX per (b,n)
__device__ float g_attnout[ROWS * NDIM];       // 16.8 MB  [b,n,h*dh]
__device__ int   g_maskkind;                   // 0=u8 1=i32 2=f32

// ---------------- mask dtype detection --------------------------------------
__global__ void detect_mask_kernel(const unsigned char* __restrict__ m) {
    __shared__ int ok_i32, ok_f32;
    if (threadIdx.x == 0) { ok_i32 = 1; ok_f32 = 1; }
    __syncthreads();
    int base = threadIdx.x * 16;
    int li = 1, lf = 1;
    for (int i = base; i < base + 16; i += 4) {
        unsigned char b0 = m[i], b1 = m[i + 1], b2 = m[i + 2], b3 = m[i + 3];
        if (!(b0 <= 1 && b1 == 0 && b2 == 0 && b3 == 0)) li = 0;
        bool fz = (b2 == 0 && b3 == 0);
        bool fo = (b2 == 0x80 && b3 == 0x3f);
        if (!(b0 == 0 && b1 == 0 && (fz || fo))) lf = 0;
    }
    if (!li) atomicAnd(&ok_i32, 0);
    if (!lf) atomicAnd(&ok_f32, 0);
    __syncthreads();
    if (threadIdx.x == 0) g_maskkind = ok_i32 ? 1 : (ok_f32 ? 2 : 0);
}

__global__ void expand_mask_kernel(const void* __restrict__ m) {
    int i = blockIdx.x * blockDim.x + threadIdx.x;
    if (i >= ROWS) return;
    int kind = g_maskkind;
    bool on;
    if (kind == 1)      on = ((const int*)m)[i] != 0;
    else if (kind == 2) on = ((const float*)m)[i] != 0.0f;
    else                on = ((const unsigned char*)m)[i] != 0;
    g_maskadd[i] = on ? 0.0f : -FLT_MAX;
}

// ---------------- RMSNorm ----------------------------------------------------
__global__ void rmsnorm_kernel(const float* __restrict__ x, const float* __restrict__ g) {
    __shared__ float red[8];
    int row = blockIdx.x;
    int tid = threadIdx.x;
    const float4* xr = (const float4*)(x + (size_t)row * NDIM);
    float4 xv = xr[tid];
    float ss = xv.x * xv.x + xv.y * xv.y + xv.z * xv.z + xv.w * xv.w;
#pragma unroll
    for (int off = 16; off; off >>= 1) ss += __shfl_xor_sync(0xffffffffu, ss, off);
    if ((tid & 31) == 0) red[tid >> 5] = ss;
    __syncthreads();
    float tot = red[0] + red[1] + red[2] + red[3] + red[4] + red[5] + red[6] + red[7];
    float inv = 32.0f / fmaxf(sqrtf(tot), 1e-12f);   // sqrt(1024)=32
    float4 gv = ((const float4*)g)[tid];
    float4 o;
    o.x = xv.x * inv * gv.x;
    o.y = xv.y * inv * gv.y;
    o.z = xv.z * inv * gv.z;
    o.w = xv.w * inv * gv.w;
    ((float4*)(g_xn + (size_t)row * NDIM))[tid] = o;
}

// ---------------- DynamicPositionBias MLP ------------------------------------
__global__ void pb_mlp_kernel(const float* __restrict__ w1, const float* __restrict__ b1,
                              const float* __restrict__ w2, const float* __restrict__ b2,
                              const float* __restrict__ w3, const float* __restrict__ b3) {
    __shared__ float h1s[16][NPB];
    __shared__ float h2s[16][NPB];
    int t = threadIdx.x;
    int r0 = blockIdx.x * 16;
    float w1t = w1[t], b1t = b1[t];
#pragma unroll
    for (int rr = 0; rr < 16; rr++) {
        int r = r0 + rr;
        float pos = (float)(r - (NN - 1));
        float z = pos * w1t + b1t;
        h1s[rr][t] = (r < PBROWS) ? z / (1.0f + __expf(-z)) : 0.0f;
    }
    __syncthreads();
    float acc[16];
    float b2t = b2[t];
#pragma unroll
    for (int rr = 0; rr < 16; rr++) acc[rr] = b2t;
#pragma unroll 4
    for (int k2 = 0; k2 < NPB; k2++) {
        float w = w2[k2 * NPB + t];
#pragma unroll
        for (int rr = 0; rr < 16; rr++) acc[rr] = fmaf(h1s[rr][k2], w, acc[rr]);
    }
#pragma unroll
    for (int rr = 0; rr < 16; rr++) {
        float z = acc[rr];
        h2s[rr][t] = z / (1.0f + __expf(-z));
    }
    __syncthreads();
    {
        int rr = t >> 4, hh = t & 15;
        float a = b3[hh];
        for (int k2 = 0; k2 < NPB; k2++) a = fmaf(h2s[rr][k2], w3[k2 * NH + hh], a);
        int r = r0 + rr;
        if (r < PBROWS) g_pb[r * NH + hh] = a;
    }
}

// ---------------- tf32 helpers -----------------------------------------------
__device__ __forceinline__ uint32_t f2tf32(float x) {
    uint32_t u;
    asm("cvt.rna.tf32.f32 %0, %1;" : "=r"(u) : "f"(x));
    return u;
}

__device__ __forceinline__ void mma_tf32(float c[4], const uint32_t a[4],
                                         uint32_t b0, uint32_t b1) {
    asm volatile(
        "mma.sync.aligned.m16n8k8.row.col.f32.tf32.tf32.f32 "
        "{%0,%1,%2,%3}, {%4,%5,%6,%7}, {%8,%9}, {%0,%1,%2,%3};\n"
        : "+f"(c[0]), "+f"(c[1]), "+f"(c[2]), "+f"(c[3])
        : "r"(a[0]), "r"(a[1]), "r"(a[2]), "r"(a[3]), "r"(b0), "r"(b1));
}

// ---------------- tf32 tensor-core GEMM 128x128x16 ----------------------------
#define GLD 136

template <int MODE>
__global__ void __launch_bounds__(256, 2)
mma_gemm_kernel(const float* __restrict__ Bw, float* __restrict__ Cout,
                const float* __restrict__ bias, int N) {
    __shared__ uint32_t As[16 * GLD];   // As[k][m], swizzled m
    __shared__ uint32_t Bs[16 * GLD];   // Bs[k][n]
    const float* A = (MODE == 0) ? g_xn : g_attnout;
    const int K = NDIM;
    const int m0 = blockIdx.y * 128;
    const int n0 = blockIdx.x * 128;
    const int tid  = threadIdx.x;
    const int warp = tid >> 5, lane = tid & 31;
    const int warpM = (warp >> 1) * 32;   // 4 warps along m
    const int warpN = (warp & 1) * 64;    // 2 warps along n

    const int ar  = tid >> 2;          // 0..63 (A rows; also ar+64)
    const int akc = (tid & 3) * 4;     // A k-offset {0,4,8,12}
    const int asw = ar ^ (8 * (tid & 3));
    const int asw2 = (ar + 64) ^ (8 * (tid & 3));
    const int bk  = tid >> 5;          // 0..7 (B k rows; also bk+8)
    const int bn4 = lane * 4;          // B col offset

    float4 pa0, pa1, pb0, pb1;
    pa0 = *(const float4*)(A + (size_t)(m0 + ar) * K + akc);
    pa1 = *(const float4*)(A + (size_t)(m0 + ar + 64) * K + akc);
    pb0 = *(const float4*)(Bw + (size_t)bk * N + n0 + bn4);
    pb1 = *(const float4*)(Bw + (size_t)(bk + 8) * N + n0 + bn4);

    float c[2][8][4];
#pragma unroll
    for (int mt = 0; mt < 2; mt++)
#pragma unroll
        for (int nt = 0; nt < 8; nt++)
#pragma unroll
            for (int i = 0; i < 4; i++) c[mt][nt][i] = 0.0f;

    for (int kt = 0; kt < K; kt += 16) {
        {
            float af0[4] = {pa0.x, pa0.y, pa0.z, pa0.w};
            float af1[4] = {pa1.x, pa1.y, pa1.z, pa1.w};
#pragma unroll
            for (int i = 0; i < 4; i++) {
                As[(akc + i) * GLD + asw]  = f2tf32(af0[i]);
                As[(akc + i) * GLD + asw2] = f2tf32(af1[i]);
            }
            uint4 b0 = make_uint4(f2tf32(pb0.x), f2tf32(pb0.y), f2tf32(pb0.z), f2tf32(pb0.w));
            uint4 b1 = make_uint4(f2tf32(pb1.x), f2tf32(pb1.y), f2tf32(pb1.z), f2tf32(pb1.w));
            *(uint4*)&Bs[bk * GLD + bn4]       = b0;
            *(uint4*)&Bs[(bk + 8) * GLD + bn4] = b1;
        }
        __syncthreads();
        if (kt + 16 < K) {
            pa0 = *(const float4*)(A + (size_t)(m0 + ar) * K + (kt + 16) + akc);
            pa1 = *(const float4*)(A + (size_t)(m0 + ar + 64) * K + (kt + 16) + akc);
            pb0 = *(const float4*)(Bw + (size_t)(kt + 16 + bk) * N + n0 + bn4);
            pb1 = *(const float4*)(Bw + (size_t)(kt + 16 + bk + 8) * N + n0 + bn4);
        }
#pragma unroll
        for (int kk = 0; kk < 16; kk += 8) {
            const int kb  = kk + (lane & 3);
            const int kb4 = kb + 4;
            const int s1 = 8 * ((kb >> 2) & 3);
            const int s2 = 8 * ((kb4 >> 2) & 3);
            uint32_t a[2][4];
#pragma unroll
            for (int mt = 0; mt < 2; mt++) {
                int r = warpM + mt * 16 + (lane >> 2);
                a[mt][0] = As[kb * GLD + (r ^ s1)];
                a[mt][1] = As[kb * GLD + ((r + 8) ^ s1)];
                a[mt][2] = As[kb4 * GLD + (r ^ s2)];
                a[mt][3] = As[kb4 * GLD + ((r + 8) ^ s2)];
            }
            uint32_t b[8][2];
#pragma unroll
            for (int nt = 0; nt < 8; nt++) {
                int cb = warpN + nt * 8 + (lane >> 2);
                b[nt][0] = Bs[kb * GLD + cb];
                b[nt][1] = Bs[kb4 * GLD + cb];
            }
#pragma unroll
            for (int mt = 0; mt < 2; mt++)
#pragma unroll
                for (int nt = 0; nt < 8; nt++)
                    mma_tf32(c[mt][nt], a[mt], b[nt][0], b[nt][1]);
        }
        __syncthreads();
    }

#pragma unroll
    for (int mt = 0; mt < 2; mt++) {
#pragma unroll
        for (int h2 = 0; h2 < 2; h2++) {
            int r = m0 + warpM + mt * 16 + (lane >> 2) + h2 * 8;
            if (MODE == 1) {
#pragma unroll
                for (int nt = 0; nt < 8; nt++) {
                    int gc = n0 + warpN + nt * 8 + 2 * (lane & 3);
                    float2 v = make_float2(c[mt][nt][h2 * 2 + 0] + bias[gc],
                                           c[mt][nt][h2 * 2 + 1] + bias[gc + 1]);
                    *(float2*)(Cout + (size_t)r * N + gc) = v;
                }
            } else {
                int bidx = r >> 11, n = r & (NN - 1);
#pragma unroll
                for (int nt = 0; nt < 8; nt++) {
                    int gc = n0 + warpN + nt * 8 + 2 * (lane & 3);
                    int which = gc >> 10, cc = gc & 1023;
                    int h = cc >> 6, d = cc & 63;
                    float* dst = (which == 0) ? g_q : (which == 1) ? g_k : g_v;
                    float2 v = make_float2(c[mt][nt][h2 * 2 + 0], c[mt][nt][h2 * 2 + 1]);
                    *(float2*)(dst + (size_t)(((bidx * NH + h) * NN) + n) * NDH + d) = v;
                }
            }
        }
    }
}

// ---------------- Flash attention: tf32 tensor cores --------------------------
// 8 warps x 16 query rows (BM=128), BN=64 key tile.
// Q in registers as A-fragments; K row-major kS[j][d] (= col-major B for QK);
// V transposed vT[d][j] (= col-major B for PV); P via smem round-trip pS[i][j]
// (per-warp-private rows -> only __syncwarp between softmax and PV).
// All fragment LDS: addr = 68*(lane>>2) + (lane&3) + const -> conflict-free.
#define AT_LD 68
#define ATT_SMEM_WORDS (64*AT_LD + 64*AT_LD + 128*AT_LD + 192 + 64)
#define ATT_SMEM_BYTES (ATT_SMEM_WORDS * 4)

__global__ void __launch_bounds__(256, 2) attn_mma_kernel() {
    extern __shared__ uint32_t smu[];
    uint32_t* kS  = smu;                   // [64][AT_LD]  K[j][d]   (tf32 bits)
    uint32_t* vT  = kS + 64 * AT_LD;       // [64][AT_LD]  V^T[d][j] (tf32 bits)
    uint32_t* pS  = vT + 64 * AT_LD;       // [128][AT_LD] P[i][j]   (tf32 bits)
    float*    pbt = (float*)(pS + 128 * AT_LD);  // [192] bias diagonal slice
    float*    mkt = pbt + 192;                   // [64]  mask add per j

    const int tid  = threadIdx.x;
    const int warp = tid >> 5, lane = tid & 31;
    const int lr = lane >> 2;          // 0..7
    const int lc = lane & 3;           // 0..3
    const int warpM = warp * 16;
    const int bh = blockIdx.y;
    const int b = bh >> 4, h = bh & 15;
    const int i0 = blockIdx.x * 128;
    const float* qg = g_q + (size_t)bh * (NN * NDH);
    const float* kg = g_k + (size_t)bh * (NN * NDH);
    const float* vg = g_v + (size_t)bh * (NN * NDH);

    const int il0 = warpM + lr;        // local row of c0/c1
    const int il1 = il0 + 8;           // local row of c2/c3

    // Q fragments (A operand), loaded once: qf[kstep][0..3]
    uint32_t qf[8][4];
    {
        const float* q0 = qg + (size_t)(i0 + il0) * NDH;
        const float* q1 = qg + (size_t)(i0 + il1) * NDH;
#pragma unroll
        for (int ks = 0; ks < 8; ks++) {
            int d0 = ks * 8 + lc;
            qf[ks][0] = f2tf32(q0[d0]);
            qf[ks][1] = f2tf32(q1[d0]);
            qf[ks][2] = f2tf32(q0[d0 + 4]);
            qf[ks][3] = f2tf32(q1[d0 + 4]);
        }
    }

    float sO[8][4];
#pragma unroll
    for (int nf = 0; nf < 8; nf++)
#pragma unroll
        for (int i = 0; i < 4; i++) sO[nf][i] = 0.0f;
    float mrow0 = -FLT_MAX, mrow1 = -FLT_MAX, lrow0 = 0.0f, lrow1 = 0.0f;

    const float scl = 0.125f;  // 1/sqrt(64)

    for (int jt = 0; jt < NN / 64; jt++) {
        const int j0 = jt * 64;
        // load K (row-major, tf32) and V (transposed, tf32)
#pragma unroll
        for (int it = 0; it < 4; it++) {
            int idx = tid + it * 256;            // 0..1023
            int row = idx >> 4;                  // 0..63
            int d4 = (idx & 15) * 4;
            float4 kv = *(const float4*)(kg + (size_t)(j0 + row) * NDH + d4);
            uint4 kt32 = make_uint4(f2tf32(kv.x), f2tf32(kv.y), f2tf32(kv.z), f2tf32(kv.w));
            *(uint4*)&kS[row * AT_LD + d4] = kt32;
            float4 vv = *(const float4*)(vg + (size_t)(j0 + row) * NDH + d4);
            vT[(d4 + 0) * AT_LD + row] = f2tf32(vv.x);
            vT[(d4 + 1) * AT_LD + row] = f2tf32(vv.y);
            vT[(d4 + 2) * AT_LD + row] = f2tf32(vv.z);
            vT[(d4 + 3) * AT_LD + row] = f2tf32(vv.w);
        }
        if (tid < 191) pbt[tid] = g_pb[(i0 - j0 + 1984 + tid) * NH + h];
        if (tid < 64)  mkt[tid] = g_maskadd[b * NN + j0 + tid];
        __syncthreads();

        // S = Q K^T
        float sS[8][4];
#pragma unroll
        for (int nf = 0; nf < 8; nf++)
#pragma unroll
            for (int i = 0; i < 4; i++) sS[nf][i] = 0.0f;
#pragma unroll
        for (int nf = 0; nf < 8; nf++) {
            const uint32_t* brow = kS + (nf * 8 + lr) * AT_LD;
#pragma unroll
            for (int ks = 0; ks < 8; ks++) {
                uint32_t b0 = brow[ks * 8 + lc];
                uint32_t b1 = brow[ks * 8 + lc + 4];
                mma_tf32(sS[nf], qf[ks], b0, b1);
            }
        }

        // scale + bias + mask, row max
        float mx0 = -FLT_MAX, mx1 = -FLT_MAX;
#pragma unroll
        for (int nf = 0; nf < 8; nf++) {
            int jl = nf * 8 + 2 * lc;
            float m0 = mkt[jl], m1 = mkt[jl + 1];
            float a00 = pbt[il0 - jl + 63] + m0;
            float a01 = pbt[il0 - jl + 62] + m1;
            float a10 = pbt[il1 - jl + 63] + m0;
            float a11 = pbt[il1 - jl + 62] + m1;
            sS[nf][0] = fmaf(sS[nf][0], scl, a00);
            sS[nf][1] = fmaf(sS[nf][1], scl, a01);
            sS[nf][2] = fmaf(sS[nf][2], scl, a10);
            sS[nf][3] = fmaf(sS[nf][3], scl, a11);
            mx0 = fmaxf(mx0, fmaxf(sS[nf][0], sS[nf][1]));
            mx1 = fmaxf(mx1, fmaxf(sS[nf][2], sS[nf][3]));
        }
        mx0 = fmaxf(mx0, __shfl_xor_sync(0xffffffffu, mx0, 1));
        mx0 = fmaxf(mx0, __shfl_xor_sync(0xffffffffu, mx0, 2));
        mx1 = fmaxf(mx1, __shfl_xor_sync(0xffffffffu, mx1, 1));
        mx1 = fmaxf(mx1, __shfl_xor_sync(0xffffffffu, mx1, 2));

        float mn0 = fmaxf(mrow0, mx0);
        float mn1 = fmaxf(mrow1, mx1);
        float al0 = __expf(mrow0 - mn0);
        float al1 = __expf(mrow1 - mn1);
        mrow0 = mn0; mrow1 = mn1;

        // exp, row sum, store P (tf32) to pS
        float rs0 = 0.0f, rs1 = 0.0f;
        uint32_t* p0 = pS + il0 * AT_LD;
        uint32_t* p1 = pS + il1 * AT_LD;
#pragma unroll
        for (int nf = 0; nf < 8; nf++) {
            int jl = nf * 8 + 2 * lc;
            float e00 = __expf(sS[nf][0] - mn0);
            float e01 = __expf(sS[nf][1] - mn0);
            float e10 = __expf(sS[nf][2] - mn1);
            float e11 = __expf(sS[nf][3] - mn1);
            rs0 += e00 + e01;
            rs1 += e10 + e11;
            *(uint2*)&p0[jl] = make_uint2(f2tf32(e00), f2tf32(e01));
            *(uint2*)&p1[jl] = make_uint2(f2tf32(e10), f2tf32(e11));
        }
        rs0 += __shfl_xor_sync(0xffffffffu, rs0, 1);
        rs0 += __shfl_xor_sync(0xffffffffu, rs0, 2);
        rs1 += __shfl_xor_sync(0xffffffffu, rs1, 1);
        rs1 += __shfl_xor_sync(0xffffffffu, rs1, 2);
        lrow0 = lrow0 * al0 + rs0;
        lrow1 = lrow1 * al1 + rs1;

        // rescale O
#pragma unroll
        for (int nf = 0; nf < 8; nf++) {
            sO[nf][0] *= al0; sO[nf][1] *= al0;
            sO[nf][2] *= al1; sO[nf][3] *= al1;
        }
        __syncwarp();   // P rows written by this warp, read cross-lane below

        // O += P V
#pragma unroll
        for (int ks = 0; ks < 8; ks++) {
            uint32_t pa[4];
            pa[0] = pS[il0 * AT_LD + ks * 8 + lc];
            pa[1] = pS[il1 * AT_LD + ks * 8 + lc];
            pa[2] = pS[il0 * AT_LD + ks * 8 + lc + 4];
            pa[3] = pS[il1 * AT_LD + ks * 8 + lc + 4];
#pragma unroll
            for (int nf = 0; nf < 8; nf++) {
                const uint32_t* vrow = vT + (nf * 8 + lr) * AT_LD;
                mma_tf32(sO[nf], pa, vrow[ks * 8 + lc], vrow[ks * 8 + lc + 4]);
            }
        }
        __syncthreads();   // protect kS/vT/pbt/mkt before next tile load
    }

    // finalize: O /= l, write [b, n, h*64 + d]
    float* og = g_attnout + (size_t)(b * NN + i0) * NDIM + h * NDH;
    float inv0 = 1.0f / lrow0;
    float inv1 = 1.0f / lrow1;
#pragma unroll
    for (int nf = 0; nf < 8; nf++) {
        int d = nf * 8 + 2 * lc;
        *(float2*)(og + (size_t)il0 * NDIM + d) = make_float2(sO[nf][0] * inv0, sO[nf][1] * inv0);
        *(float2*)(og + (size_t)il1 * NDIM + d) = make_float2(sO[nf][2] * inv1, sO[nf][3] * inv1);
    }
}

// ---------------- launch ------------------------------------------------------
extern "C" void kernel_launch(void* const* d_in, const int* in_sizes, int n_in,
                              void* d_out, int out_size) {
    const float* x      = (const float*)d_in[0];
    const void*  mask   = d_in[1];
    const float* g      = (const float*)d_in[2];
    const float* w_qkv  = (const float*)d_in[3];
    const float* w_out  = (const float*)d_in[4];
    const float* b_out  = (const float*)d_in[5];
    const float* pb_w1  = (const float*)d_in[6];
    const float* pb_b1  = (const float*)d_in[7];
    const float* pb_w2  = (const float*)d_in[8];
    const float* pb_b2  = (const float*)d_in[9];
    const float* pb_w3  = (const float*)d_in[10];
    const float* pb_b3  = (const float*)d_in[11];
    float* out = (float*)d_out;

    detect_mask_kernel<<<1, 256>>>((const unsigned char*)mask);
    expand_mask_kernel<<<ROWS / 256, 256>>>(mask);
    rmsnorm_kernel<<<ROWS, 256>>>(x, g);
    pb_mlp_kernel<<<256, 256>>>(pb_w1, pb_b1, pb_w2, pb_b2, pb_w3, pb_b3);

    // QKV GEMM: [4096,1024] @ [1024,3072]  (tf32 tensor cores)
    mma_gemm_kernel<0><<<dim3(3 * NDIM / 128, ROWS / 128), 256>>>(w_qkv, nullptr, nullptr, 3 * NDIM);

    // Flash attention (tf32 tensor cores)
    cudaFuncSetAttribute(attn_mma_kernel, cudaFuncAttributeMaxDynamicSharedMemorySize, ATT_SMEM_BYTES);
    attn_mma_kernel<<<dim3(NN / 128, NB * NH), 256, ATT_SMEM_BYTES>>>();

    // Output projection: [4096,1024] @ [1024,1024] + b_out  (tf32 tensor cores)
    mma_gemm_kernel<1><<<dim3(NDIM / 128, ROWS / 128), 256>>>(w_out, out, b_out, NDIM);
}